// round 1
// baseline (speedup 1.0000x reference)
#include <cuda_runtime.h>

#define N_NODES 8192
#define D 128
#define KNBR 8
#define LN_EPS 1e-5f
#define NEGBIG -1e30f

// ---------------- scratch (device globals: no allocation allowed) ----------
__device__ float g_buf0[N_NODES * D];
__device__ float g_buf1[N_NODES * D];
__device__ float g_buf2[N_NODES * D];
__device__ float g_dinv[N_NODES];
__device__ int   g_keptn[N_NODES * KNBR];
__device__ int   g_kcnt[N_NODES];

// ---------------- graph prep: dedup neighbors, degree^-1/2 -----------------
__global__ void prep_kernel(const int* __restrict__ neigh,
                            const int* __restrict__ nbrc) {
    int i = blockIdx.x * blockDim.x + threadIdx.x;
    if (i >= N_NODES) return;
    int cnt = nbrc[i];
    cnt = cnt > KNBR ? KNBR : (cnt < 0 ? 0 : cnt);
    int kept[KNBR];
    int kc = 0;
    for (int k = 0; k < cnt; ++k) {
        int nb = neigh[i * KNBR + k];
        if (nb == i) continue;          // merges with self-loop (diag set to 1)
        bool dup = false;
        for (int t = 0; t < kc; ++t) if (kept[t] == nb) dup = true;
        if (!dup) kept[kc++] = nb;      // A = min(A, 1): multi-edges count once
    }
    for (int t = 0; t < kc; ++t) g_keptn[i * KNBR + t] = kept[t];
    g_kcnt[i] = kc;
    g_dinv[i] = rsqrtf((float)(kc + 1));   // +1 for the self loop
}

// ---------------- fused GEMM: C = [A1|A2] @ W^T + b, epilogue variants -----
// W is row-major [128][wstride]; A2 may be null (K=128) or set (K=256).
// mode 0: plain   mode 1: relu   mode 2: LN(relu(C)+res)
#define TM 32
#define M_PLAIN 0
#define M_RELU  1
#define M_LN    2

__global__ __launch_bounds__(256)
void gemm_kernel(const float* __restrict__ A1, const float* __restrict__ A2,
                 const float* __restrict__ W, int wstride,
                 const float* __restrict__ bias,
                 const float* __restrict__ res,
                 const float* __restrict__ lng, const float* __restrict__ lnb,
                 float* __restrict__ out, int ostride, int ooff, int mode) {
    __shared__ float sA[TM][64];
    __shared__ float sW[64][132];   // sW[k][n], transposed; pad keeps f4 aligned

    const int tid = threadIdx.x;
    const int tx = tid & 31;        // col group: cols tx*4 .. tx*4+3
    const int ty = tid >> 5;        // row group (= warp id): rows ty*4 .. ty*4+3
    const int m0 = blockIdx.x * TM;

    float acc[4][4] = {};
    const int nseg = A2 ? 4 : 2;    // K in chunks of 64

    for (int seg = 0; seg < nseg; ++seg) {
        const float* A = (seg < 2) ? A1 : A2;
        const int akoff = (seg & 1) * 64;
        const int wkoff = seg * 64;
        __syncthreads();
        // stage A tile: 32 rows x 64 cols
        {
            int t = tid;
#pragma unroll
            for (int it = 0; it < 2; ++it, t += 256) {
                int r = t >> 4, c4 = (t & 15) << 2;
                *(float4*)&sA[r][c4] =
                    *(const float4*)&A[(m0 + r) * D + akoff + c4];
            }
        }
        // stage W chunk transposed: sW[k][n] = W[n][wkoff+k]
        {
            int t = tid;
#pragma unroll
            for (int it = 0; it < 8; ++it, t += 256) {
                int n = t >> 4, k4 = (t & 15) << 2;
                float4 w = *(const float4*)&W[n * wstride + wkoff + k4];
                sW[k4 + 0][n] = w.x;
                sW[k4 + 1][n] = w.y;
                sW[k4 + 2][n] = w.z;
                sW[k4 + 3][n] = w.w;
            }
        }
        __syncthreads();
#pragma unroll 8
        for (int k = 0; k < 64; ++k) {
            float4 w4 = *(const float4*)&sW[k][tx << 2];
            float a0 = sA[(ty << 2) + 0][k];
            float a1 = sA[(ty << 2) + 1][k];
            float a2 = sA[(ty << 2) + 2][k];
            float a3 = sA[(ty << 2) + 3][k];
            acc[0][0] += a0 * w4.x; acc[0][1] += a0 * w4.y;
            acc[0][2] += a0 * w4.z; acc[0][3] += a0 * w4.w;
            acc[1][0] += a1 * w4.x; acc[1][1] += a1 * w4.y;
            acc[1][2] += a1 * w4.z; acc[1][3] += a1 * w4.w;
            acc[2][0] += a2 * w4.x; acc[2][1] += a2 * w4.y;
            acc[2][2] += a2 * w4.z; acc[2][3] += a2 * w4.w;
            acc[3][0] += a3 * w4.x; acc[3][1] += a3 * w4.y;
            acc[3][2] += a3 * w4.z; acc[3][3] += a3 * w4.w;
        }
    }

    // ------------- epilogue -------------
    const int n0 = tx << 2;
    const int mb = m0 + (ty << 2);
    float bj[4] = { bias[n0], bias[n0 + 1], bias[n0 + 2], bias[n0 + 3] };

    if (mode == M_PLAIN) {
#pragma unroll
        for (int i = 0; i < 4; ++i)
#pragma unroll
            for (int j = 0; j < 4; ++j)
                out[(mb + i) * ostride + ooff + n0 + j] = acc[i][j] + bj[j];
    } else if (mode == M_RELU) {
#pragma unroll
        for (int i = 0; i < 4; ++i)
#pragma unroll
            for (int j = 0; j < 4; ++j)
                out[(mb + i) * ostride + ooff + n0 + j] =
                    fmaxf(acc[i][j] + bj[j], 0.f);
    } else {
        // LN(relu(C)+res): each warp (fixed ty) owns 4 complete rows
        float v[4][4];
#pragma unroll
        for (int i = 0; i < 4; ++i)
#pragma unroll
            for (int j = 0; j < 4; ++j)
                v[i][j] = fmaxf(acc[i][j] + bj[j], 0.f) +
                          res[(mb + i) * D + n0 + j];
        float gj[4] = { lng[n0], lng[n0 + 1], lng[n0 + 2], lng[n0 + 3] };
        float oj[4] = { lnb[n0], lnb[n0 + 1], lnb[n0 + 2], lnb[n0 + 3] };
#pragma unroll
        for (int i = 0; i < 4; ++i) {
            float s  = v[i][0] + v[i][1] + v[i][2] + v[i][3];
            float ss = v[i][0] * v[i][0] + v[i][1] * v[i][1] +
                       v[i][2] * v[i][2] + v[i][3] * v[i][3];
#pragma unroll
            for (int off = 16; off; off >>= 1) {
                s  += __shfl_xor_sync(0xffffffffu, s,  off);
                ss += __shfl_xor_sync(0xffffffffu, ss, off);
            }
            float mean = s * (1.0f / 128.0f);
            float var  = ss * (1.0f / 128.0f) - mean * mean;
            float rstd = rsqrtf(var + LN_EPS);
#pragma unroll
            for (int j = 0; j < 4; ++j)
                out[(mb + i) * ostride + ooff + n0 + j] =
                    (v[i][j] - mean) * rstd * gj[j] + oj[j];
        }
    }
}

// ---------------- GCN: h = LN(relu(Ah @ nxt) + res)  (warp per node) -------
__global__ __launch_bounds__(256)
void prop_ln_kernel(const float* __restrict__ nxt, const float* __restrict__ res,
                    const float* __restrict__ lng, const float* __restrict__ lnb,
                    float* __restrict__ out, int ostride, int ooff) {
    const int lane = threadIdx.x & 31;
    const int i = (blockIdx.x << 3) + (threadIdx.x >> 5);
    const float di = g_dinv[i];

    float acc[4];
    const float* self = nxt + i * D;
#pragma unroll
    for (int q = 0; q < 4; ++q) acc[q] = di * self[lane + 32 * q];

    const int kc = g_kcnt[i];
    const int* kn = &g_keptn[i * KNBR];
    for (int k = 0; k < kc; ++k) {
        int j = kn[k];
        float dj = g_dinv[j];
        const float* row = nxt + j * D;
#pragma unroll
        for (int q = 0; q < 4; ++q) acc[q] += dj * row[lane + 32 * q];
    }

    float v[4], s = 0.f, ss = 0.f;
    const float* rr = res + i * D;
#pragma unroll
    for (int q = 0; q < 4; ++q) {
        float p = fmaxf(di * acc[q], 0.f);
        v[q] = p + rr[lane + 32 * q];
        s += v[q];
        ss += v[q] * v[q];
    }
#pragma unroll
    for (int off = 16; off; off >>= 1) {
        s  += __shfl_xor_sync(0xffffffffu, s,  off);
        ss += __shfl_xor_sync(0xffffffffu, ss, off);
    }
    float mean = s * (1.0f / 128.0f);
    float rstd = rsqrtf(ss * (1.0f / 128.0f) - mean * mean + LN_EPS);
#pragma unroll
    for (int q = 0; q < 4; ++q) {
        int d = lane + 32 * q;
        out[i * ostride + ooff + d] = (v[q] - mean) * rstd * lng[d] + lnb[d];
    }
}

// ---------------- SAGE max-pool over valid neighbors (warp per node) -------
__global__ __launch_bounds__(256)
void pool_kernel(const float* __restrict__ src, const int* __restrict__ neigh,
                 const int* __restrict__ nbrc, float* __restrict__ out) {
    const int lane = threadIdx.x & 31;
    const int i = (blockIdx.x << 3) + (threadIdx.x >> 5);
    int cnt = nbrc[i];
    cnt = cnt > KNBR ? KNBR : (cnt < 0 ? 0 : cnt);
    if (cnt == 0) {
#pragma unroll
        for (int q = 0; q < 4; ++q) out[i * D + lane + 32 * q] = 0.f;
        return;
    }
    float m[4] = { NEGBIG, NEGBIG, NEGBIG, NEGBIG };
    for (int k = 0; k < cnt; ++k) {
        int j = neigh[i * KNBR + k];
        const float* row = src + j * D;
#pragma unroll
        for (int q = 0; q < 4; ++q) m[q] = fmaxf(m[q], row[lane + 32 * q]);
    }
#pragma unroll
    for (int q = 0; q < 4; ++q) out[i * D + lane + 32 * q] = m[q];
}

// ---------------- driver ----------------------------------------------------
extern "C" void kernel_launch(void* const* d_in, const int* in_sizes, int n_in,
                              void* d_out, int out_size) {
    const float* x    = (const float*)d_in[0];
    const int*   nei  = (const int*)  d_in[1];
    const int*   nbc  = (const int*)  d_in[2];
    const float* gW   = (const float*)d_in[3];   // [3,128,128]
    const float* gb   = (const float*)d_in[4];   // [3,128]
    const float* glg  = (const float*)d_in[5];
    const float* glb  = (const float*)d_in[6];
    const float* pW   = (const float*)d_in[7];   // [128,128]
    const float* pb   = (const float*)d_in[8];
    const float* mW   = (const float*)d_in[9];   // [3,128,256]
    const float* mb   = (const float*)d_in[10];  // [3,128]
    const float* slg  = (const float*)d_in[11];  // [2,128]
    const float* slb  = (const float*)d_in[12];
    float* out = (float*)d_out;

    float *b0, *b1, *b2;
    cudaGetSymbolAddress((void**)&b0, g_buf0);
    cudaGetSymbolAddress((void**)&b1, g_buf1);
    cudaGetSymbolAddress((void**)&b2, g_buf2);

    const int GB = N_NODES / TM;       // 256 gemm blocks
    const int WB = N_NODES / 8;        // 1024 warp-per-node blocks

    prep_kernel<<<N_NODES / 256, 256>>>(nei, nbc);

    // ---- GCN branch ----
    // layer 0: nxt0 = x@W0^T+b0 ; h = LN(relu(Ah@nxt0) + nxt0)
    gemm_kernel<<<GB, 256>>>(x, nullptr, gW, D, gb,
                             nullptr, nullptr, nullptr, b0, D, 0, M_PLAIN);
    prop_ln_kernel<<<WB, 256>>>(b0, b0, glg, glb, b1, D, 0);
    // layer 1
    gemm_kernel<<<GB, 256>>>(b1, nullptr, gW + D * D, D, gb + D,
                             nullptr, nullptr, nullptr, b0, D, 0, M_PLAIN);
    prop_ln_kernel<<<WB, 256>>>(b0, b1, glg + D, glb + D, b1, D, 0);
    // layer 2 -> out[:, 0:128]
    gemm_kernel<<<GB, 256>>>(b1, nullptr, gW + 2 * D * D, D, gb + 2 * D,
                             nullptr, nullptr, nullptr, b0, D, 0, M_PLAIN);
    prop_ln_kernel<<<WB, 256>>>(b0, b1, glg + 2 * D, glb + 2 * D, out, 2 * D, 0);

    // ---- SAGE branch ----
    // ne1 = relu(x@poolW^T+pb)
    gemm_kernel<<<GB, 256>>>(x, nullptr, pW, D, pb,
                             nullptr, nullptr, nullptr, b0, D, 0, M_RELU);
    pool_kernel<<<WB, 256>>>(b0, nei, nbc, b1);
    // s = relu([x | pool] @ W0^T + b0)
    gemm_kernel<<<GB, 256>>>(x, b1, mW, 2 * D, mb,
                             nullptr, nullptr, nullptr, b2, D, 0, M_RELU);
    // layer 1: s = LN(relu([s | pool(s)]@W1^T+b1) + s)
    pool_kernel<<<WB, 256>>>(b2, nei, nbc, b1);
    gemm_kernel<<<GB, 256>>>(b2, b1, mW + D * 2 * D, 2 * D, mb + D,
                             b2, slg, slb, b2, D, 0, M_LN);
    // layer 2 -> out[:, 128:256]
    pool_kernel<<<WB, 256>>>(b2, nei, nbc, b1);
    gemm_kernel<<<GB, 256>>>(b2, b1, mW + 2 * D * 2 * D, 2 * D, mb + 2 * D,
                             b2, slg + D, slb + D, out, 2 * D, D, M_LN);
}

// round 2
// speedup vs baseline: 1.0124x; 1.0124x over previous
#include <cuda_runtime.h>

#define N_NODES 8192
#define D 128
#define KNBR 8
#define LN_EPS 1e-5f
#define NEGBIG -1e30f

// ---------------- scratch (device globals: no allocation allowed) ----------
__device__ float g_buf0[N_NODES * D];
__device__ float g_buf1[N_NODES * D];
__device__ float g_buf2[N_NODES * D];
__device__ float g_dinv[N_NODES];
__device__ int   g_keptn[N_NODES * KNBR];
__device__ int   g_kcnt[N_NODES];

// ---------------- graph prep: dedup neighbors, degree^-1/2 -----------------
__global__ void prep_kernel(const int* __restrict__ neigh,
                            const int* __restrict__ nbrc) {
    int i = blockIdx.x * blockDim.x + threadIdx.x;
    if (i >= N_NODES) return;
    int cnt = nbrc[i];
    cnt = cnt > KNBR ? KNBR : (cnt < 0 ? 0 : cnt);
    int kept[KNBR];
    int kc = 0;
    for (int k = 0; k < cnt; ++k) {
        int nb = neigh[i * KNBR + k];
        if (nb == i) continue;          // merges with self-loop (diag set to 1)
        bool dup = false;
        for (int t = 0; t < kc; ++t) if (kept[t] == nb) dup = true;
        if (!dup) kept[kc++] = nb;      // A = min(A, 1): multi-edges count once
    }
    for (int t = 0; t < kc; ++t) g_keptn[i * KNBR + t] = kept[t];
    g_kcnt[i] = kc;
    g_dinv[i] = rsqrtf((float)(kc + 1));   // +1 for the self loop
}

// ---------------- fused GEMM: C = [A1|A2] @ W^T + b, epilogue variants -----
// W is row-major [128][wstride]; A2 may be null (K=128) or set (K=256).
// mode 0: plain   mode 1: relu   mode 2: LN(relu(C)+res)
#define TM 32
#define M_PLAIN 0
#define M_RELU  1
#define M_LN    2

__global__ __launch_bounds__(256)
void gemm_kernel(const float* __restrict__ A1, const float* __restrict__ A2,
                 const float* __restrict__ W, int wstride,
                 const float* __restrict__ bias,
                 const float* __restrict__ res,
                 const float* __restrict__ lng, const float* __restrict__ lnb,
                 float* __restrict__ out, int ostride, int ooff, int mode) {
    __shared__ float sA[TM][64];
    __shared__ float sW[64][132];   // sW[k][n], transposed; pad keeps f4 aligned

    const int tid = threadIdx.x;
    const int tx = tid & 31;        // col group: cols tx*4 .. tx*4+3
    const int ty = tid >> 5;        // row group (= warp id): rows ty*4 .. ty*4+3
    const int m0 = blockIdx.x * TM;

    float acc[4][4] = {};
    const int nseg = A2 ? 4 : 2;    // K in chunks of 64

    for (int seg = 0; seg < nseg; ++seg) {
        const float* A = (seg < 2) ? A1 : A2;
        const int akoff = (seg & 1) * 64;
        const int wkoff = seg * 64;
        __syncthreads();
        // stage A tile: 32 rows x 64 cols
        {
            int t = tid;
#pragma unroll
            for (int it = 0; it < 2; ++it, t += 256) {
                int r = t >> 4, c4 = (t & 15) << 2;
                *(float4*)&sA[r][c4] =
                    *(const float4*)&A[(m0 + r) * D + akoff + c4];
            }
        }
        // stage W chunk transposed: sW[k][n] = W[n][wkoff+k]
        {
            int t = tid;
#pragma unroll
            for (int it = 0; it < 8; ++it, t += 256) {
                int n = t >> 4, k4 = (t & 15) << 2;
                float4 w = *(const float4*)&W[n * wstride + wkoff + k4];
                sW[k4 + 0][n] = w.x;
                sW[k4 + 1][n] = w.y;
                sW[k4 + 2][n] = w.z;
                sW[k4 + 3][n] = w.w;
            }
        }
        __syncthreads();
#pragma unroll 8
        for (int k = 0; k < 64; ++k) {
            float4 w4 = *(const float4*)&sW[k][tx << 2];
            float a0 = sA[(ty << 2) + 0][k];
            float a1 = sA[(ty << 2) + 1][k];
            float a2 = sA[(ty << 2) + 2][k];
            float a3 = sA[(ty << 2) + 3][k];
            acc[0][0] += a0 * w4.x; acc[0][1] += a0 * w4.y;
            acc[0][2] += a0 * w4.z; acc[0][3] += a0 * w4.w;
            acc[1][0] += a1 * w4.x; acc[1][1] += a1 * w4.y;
            acc[1][2] += a1 * w4.z; acc[1][3] += a1 * w4.w;
            acc[2][0] += a2 * w4.x; acc[2][1] += a2 * w4.y;
            acc[2][2] += a2 * w4.z; acc[2][3] += a2 * w4.w;
            acc[3][0] += a3 * w4.x; acc[3][1] += a3 * w4.y;
            acc[3][2] += a3 * w4.z; acc[3][3] += a3 * w4.w;
        }
    }

    // ------------- epilogue -------------
    const int n0 = tx << 2;
    const int mb = m0 + (ty << 2);
    float bj[4] = { bias[n0], bias[n0 + 1], bias[n0 + 2], bias[n0 + 3] };

    if (mode == M_PLAIN) {
#pragma unroll
        for (int i = 0; i < 4; ++i)
#pragma unroll
            for (int j = 0; j < 4; ++j)
                out[(mb + i) * ostride + ooff + n0 + j] = acc[i][j] + bj[j];
    } else if (mode == M_RELU) {
#pragma unroll
        for (int i = 0; i < 4; ++i)
#pragma unroll
            for (int j = 0; j < 4; ++j)
                out[(mb + i) * ostride + ooff + n0 + j] =
                    fmaxf(acc[i][j] + bj[j], 0.f);
    } else {
        // LN(relu(C)+res): each warp (fixed ty) owns 4 complete rows
        float v[4][4];
#pragma unroll
        for (int i = 0; i < 4; ++i)
#pragma unroll
            for (int j = 0; j < 4; ++j)
                v[i][j] = fmaxf(acc[i][j] + bj[j], 0.f) +
                          res[(mb + i) * D + n0 + j];
        float gj[4] = { lng[n0], lng[n0 + 1], lng[n0 + 2], lng[n0 + 3] };
        float oj[4] = { lnb[n0], lnb[n0 + 1], lnb[n0 + 2], lnb[n0 + 3] };
#pragma unroll
        for (int i = 0; i < 4; ++i) {
            float s  = v[i][0] + v[i][1] + v[i][2] + v[i][3];
            float ss = v[i][0] * v[i][0] + v[i][1] * v[i][1] +
                       v[i][2] * v[i][2] + v[i][3] * v[i][3];
#pragma unroll
            for (int off = 16; off; off >>= 1) {
                s  += __shfl_xor_sync(0xffffffffu, s,  off);
                ss += __shfl_xor_sync(0xffffffffu, ss, off);
            }
            float mean = s * (1.0f / 128.0f);
            float var  = ss * (1.0f / 128.0f) - mean * mean;
            float rstd = rsqrtf(var + LN_EPS);
#pragma unroll
            for (int j = 0; j < 4; ++j)
                out[(mb + i) * ostride + ooff + n0 + j] =
                    (v[i][j] - mean) * rstd * gj[j] + oj[j];
        }
    }
}

// ---------------- GCN: h = LN(relu(Ah @ nxt) + res)  (warp per node) -------
__global__ __launch_bounds__(256)
void prop_ln_kernel(const float* __restrict__ nxt, const float* __restrict__ res,
                    const float* __restrict__ lng, const float* __restrict__ lnb,
                    float* __restrict__ out, int ostride, int ooff) {
    const int lane = threadIdx.x & 31;
    const int i = (blockIdx.x << 3) + (threadIdx.x >> 5);
    const float di = g_dinv[i];

    float acc[4];
    const float* self = nxt + i * D;
#pragma unroll
    for (int q = 0; q < 4; ++q) acc[q] = di * self[lane + 32 * q];

    const int kc = g_kcnt[i];
    const int* kn = &g_keptn[i * KNBR];
    for (int k = 0; k < kc; ++k) {
        int j = kn[k];
        float dj = g_dinv[j];
        const float* row = nxt + j * D;
#pragma unroll
        for (int q = 0; q < 4; ++q) acc[q] += dj * row[lane + 32 * q];
    }

    float v[4], s = 0.f, ss = 0.f;
    const float* rr = res + i * D;
#pragma unroll
    for (int q = 0; q < 4; ++q) {
        float p = fmaxf(di * acc[q], 0.f);
        v[q] = p + rr[lane + 32 * q];
        s += v[q];
        ss += v[q] * v[q];
    }
#pragma unroll
    for (int off = 16; off; off >>= 1) {
        s  += __shfl_xor_sync(0xffffffffu, s,  off);
        ss += __shfl_xor_sync(0xffffffffu, ss, off);
    }
    float mean = s * (1.0f / 128.0f);
    float rstd = rsqrtf(ss * (1.0f / 128.0f) - mean * mean + LN_EPS);
#pragma unroll
    for (int q = 0; q < 4; ++q) {
        int d = lane + 32 * q;
        out[i * ostride + ooff + d] = (v[q] - mean) * rstd * lng[d] + lnb[d];
    }
}

// ---------------- SAGE max-pool over valid neighbors (warp per node) -------
__global__ __launch_bounds__(256)
void pool_kernel(const float* __restrict__ src, const int* __restrict__ neigh,
                 const int* __restrict__ nbrc, float* __restrict__ out) {
    const int lane = threadIdx.x & 31;
    const int i = (blockIdx.x << 3) + (threadIdx.x >> 5);
    int cnt = nbrc[i];
    cnt = cnt > KNBR ? KNBR : (cnt < 0 ? 0 : cnt);
    if (cnt == 0) {
#pragma unroll
        for (int q = 0; q < 4; ++q) out[i * D + lane + 32 * q] = 0.f;
        return;
    }
    float m[4] = { NEGBIG, NEGBIG, NEGBIG, NEGBIG };
    for (int k = 0; k < cnt; ++k) {
        int j = neigh[i * KNBR + k];
        const float* row = src + j * D;
#pragma unroll
        for (int q = 0; q < 4; ++q) m[q] = fmaxf(m[q], row[lane + 32 * q]);
    }
#pragma unroll
    for (int q = 0; q < 4; ++q) out[i * D + lane + 32 * q] = m[q];
}

// ---------------- driver ----------------------------------------------------
extern "C" void kernel_launch(void* const* d_in, const int* in_sizes, int n_in,
                              void* d_out, int out_size) {
    const float* x    = (const float*)d_in[0];
    const int*   nei  = (const int*)  d_in[1];
    const int*   nbc  = (const int*)  d_in[2];
    const float* gW   = (const float*)d_in[3];   // [3,128,128]
    const float* gb   = (const float*)d_in[4];   // [3,128]
    const float* glg  = (const float*)d_in[5];
    const float* glb  = (const float*)d_in[6];
    const float* pW   = (const float*)d_in[7];   // [128,128]
    const float* pb   = (const float*)d_in[8];
    const float* mW   = (const float*)d_in[9];   // [3,128,256]
    const float* mb   = (const float*)d_in[10];  // [3,128]
    const float* slg  = (const float*)d_in[11];  // [2,128]
    const float* slb  = (const float*)d_in[12];
    float* out = (float*)d_out;

    float *b0, *b1, *b2;
    cudaGetSymbolAddress((void**)&b0, g_buf0);
    cudaGetSymbolAddress((void**)&b1, g_buf1);
    cudaGetSymbolAddress((void**)&b2, g_buf2);

    const int GB = N_NODES / TM;       // 256 gemm blocks
    const int WB = N_NODES / 8;        // 1024 warp-per-node blocks

    prep_kernel<<<N_NODES / 256, 256>>>(nei, nbc);

    // ---- GCN branch ----
    // layer 0: nxt0 = x@W0^T+b0 ; h = LN(relu(Ah@nxt0) + nxt0)
    gemm_kernel<<<GB, 256>>>(x, nullptr, gW, D, gb,
                             nullptr, nullptr, nullptr, b0, D, 0, M_PLAIN);
    prop_ln_kernel<<<WB, 256>>>(b0, b0, glg, glb, b1, D, 0);
    // layer 1
    gemm_kernel<<<GB, 256>>>(b1, nullptr, gW + D * D, D, gb + D,
                             nullptr, nullptr, nullptr, b0, D, 0, M_PLAIN);
    prop_ln_kernel<<<WB, 256>>>(b0, b1, glg + D, glb + D, b1, D, 0);
    // layer 2 -> out[:, 0:128]
    gemm_kernel<<<GB, 256>>>(b1, nullptr, gW + 2 * D * D, D, gb + 2 * D,
                             nullptr, nullptr, nullptr, b0, D, 0, M_PLAIN);
    prop_ln_kernel<<<WB, 256>>>(b0, b1, glg + 2 * D, glb + 2 * D, out, 2 * D, 0);

    // ---- SAGE branch ----
    // ne1 = relu(x@poolW^T+pb)
    gemm_kernel<<<GB, 256>>>(x, nullptr, pW, D, pb,
                             nullptr, nullptr, nullptr, b0, D, 0, M_RELU);
    pool_kernel<<<WB, 256>>>(b0, nei, nbc, b1);
    // s = relu([x | pool] @ W0^T + b0)
    gemm_kernel<<<GB, 256>>>(x, b1, mW, 2 * D, mb,
                             nullptr, nullptr, nullptr, b2, D, 0, M_RELU);
    // layer 1: s = LN(relu([s | pool(s)]@W1^T+b1) + s)
    pool_kernel<<<WB, 256>>>(b2, nei, nbc, b1);
    gemm_kernel<<<GB, 256>>>(b2, b1, mW + D * 2 * D, 2 * D, mb + D,
                             b2, slg, slb, b2, D, 0, M_LN);
    // layer 2 -> out[:, 128:256]
    pool_kernel<<<WB, 256>>>(b2, nei, nbc, b1);
    gemm_kernel<<<GB, 256>>>(b2, b1, mW + 2 * D * 2 * D, 2 * D, mb + 2 * D,
                             b2, slg + D, slb + D, out, 2 * D, D, M_LN);
}